// round 6
// baseline (speedup 1.0000x reference)
#include <cuda_runtime.h>
#include <cuda_bf16.h>
#include <cstdint>

#define CB   2
#define CC   128
#define CH   20
#define CW   20
#define CHW  400
#define CEPS 1e-5f

// ======================= helpers =======================
__device__ __forceinline__ uint32_t smem_to_u32(const void* p) {
    uint32_t a;
    asm("{ .reg .u64 t; cvta.to.shared.u64 t, %1; cvt.u32.u64 %0, t; }" : "=r"(a) : "l"(p));
    return a;
}
__device__ __forceinline__ void ldsm_x4(unsigned* r, uint32_t addr) {
    asm volatile("ldmatrix.sync.aligned.m8n8.x4.shared.b16 {%0,%1,%2,%3}, [%4];"
        : "=r"(r[0]), "=r"(r[1]), "=r"(r[2]), "=r"(r[3]) : "r"(addr));
}
__device__ __forceinline__ void mma16816(float* d, const unsigned* a, const unsigned* b) {
    asm volatile("mma.sync.aligned.m16n8k16.row.col.f32.bf16.bf16.f32 "
        "{%0,%1,%2,%3}, {%4,%5,%6,%7}, {%8,%9}, {%0,%1,%2,%3};"
        : "+f"(d[0]), "+f"(d[1]), "+f"(d[2]), "+f"(d[3])
        : "r"(a[0]), "r"(a[1]), "r"(a[2]), "r"(a[3]), "r"(b[0]), "r"(b[1]));
}

// ======================= device scratch =======================
__device__ float g_w1t[CC * CC];
__device__ float g_bias1[CC];
__device__ float g_w2t[CC * CC];
__device__ float g_bias2[CC];
__device__ float g_wr1ft[256 * CC];
__device__ float g_biasr1[CC];
__device__ float g_T[9 * CC * CC];
__device__ float g_biasr2[CC];
__device__ float g_wr3[CC];
__device__ float g_bias3s[1];
__device__ float g_A0[200 * CC];
__device__ float g_A1[200 * CC];
__device__ float g_feat[CB * CHW * CC];
__device__ float g_featT[CB * CC * CHW];
__device__ float g_scores[CB * CHW * CHW];
__device__ __align__(16) __nv_bfloat16 g_wcv[9 * CC * CC]; // [tap][c2][ch] folded bf16
__device__ float2 g_lut[2048];

struct Params { const float* p[26]; };

__device__ __forceinline__ float siluf(float x) {
    float s = 1.f / (1.f + __expf(-x));
    return x * s;
}
__device__ __forceinline__ float lut_silu(const float2* lut, float x) {
    float xc = fminf(fmaxf(x, -16.0f), 15.99993f);
    float fi = (xc + 16.0f) * 64.0f;
    int i = (int)fi;
    float fr = fi - (float)i;
    float2 e = lut[i];
    float y = fmaf(fr, e.y, e.x);
    return (x >= 16.0f) ? x : y;
}

// ======================= K0: fold =======================
__global__ void fold_kernel(Params P) {
    const float* w1  = P.p[1];
    const float* g1  = P.p[2];  const float* b1 = P.p[3];
    const float* m1  = P.p[4];  const float* v1 = P.p[5];
    const float* w2  = P.p[6];
    const float* g2  = P.p[7];  const float* b2 = P.p[8];
    const float* m2  = P.p[9];  const float* v2 = P.p[10];
    const float* wr1 = P.p[11];
    const float* gr1 = P.p[12]; const float* br1 = P.p[13];
    const float* mr1 = P.p[14]; const float* vr1 = P.p[15];
    const float* wr2 = P.p[16];
    const float* gr2 = P.p[17]; const float* br2 = P.p[18];
    const float* mr2 = P.p[19]; const float* vr2 = P.p[20];
    const float* wr3 = P.p[21];
    const float* gr3 = P.p[22]; const float* br3 = P.p[23];
    const float* mr3 = P.p[24]; const float* vr3 = P.p[25];

    int t = blockIdx.x * blockDim.x + threadIdx.x;
    int stride = gridDim.x * blockDim.x;

    for (int i = t; i < CC * CC; i += stride) {
        int c = i >> 7, k = i & 127;
        float s  = g1[c] * rsqrtf(v1[c] + CEPS);
        g_w1t[k * CC + c] = w1[i] * s;
        float s2 = g2[c] * rsqrtf(v2[c] + CEPS);
        g_w2t[k * CC + c] = w2[i] * s2;
    }
    for (int i = t; i < 256 * CC; i += stride) {
        int cp = i >> 7, o = i & 127;
        float sr = gr1[o] * rsqrtf(vr1[o] + CEPS);
        g_wr1ft[cp * CC + o] = wr1[o * 256 + cp] * sr;
    }
    // conv weights bf16 [tap][c2][ch]
    for (int i = t; i < 9 * CC * CC; i += stride) {
        int di = i >> 14; int r = i & 16383;
        int c2 = r >> 7; int c = r & 127;
        float s = gr2[c2] * rsqrtf(vr2[c2] + CEPS);
        g_wcv[i] = __float2bfloat16(wr2[(c2 * CC + c) * 9 + di] * s);
    }
    // silu LUT
    for (int i = t; i < 2048; i += stride) {
        float x0 = -16.0f + (float)i * 0.015625f;
        float x1 = x0 + 0.015625f;
        float s0 = x0 / (1.0f + expf(-x0));
        float s1 = x1 / (1.0f + expf(-x1));
        g_lut[i] = make_float2(s0, s1 - s0);
    }
    // border-class tap sums for fi path
    for (int i = t; i < 9 * CC * CC; i += stride) {
        int cls = i >> 14; int r = i & 16383;
        int o = r >> 7; int o2 = r & 127;
        int rc = cls / 3, ccl = cls - rc * 3;
        float s = gr2[o2] * rsqrtf(vr2[o2] + CEPS);
        float acc = 0.f;
        #pragma unroll
        for (int k = 0; k < 9; k++) {
            int ky = k / 3, kx = k - ky * 3;
            bool rok = (rc == 1) || (rc == 0 ? (ky >= 1) : (ky <= 1));
            bool cok = (ccl == 1) || (ccl == 0 ? (kx >= 1) : (kx <= 1));
            if (rok && cok) acc += wr2[(o2 * CC + o) * 9 + k];
        }
        g_T[i] = acc * s;
    }
    if (t < CC) {
        float s1 = g1[t] * rsqrtf(v1[t] + CEPS);
        g_bias1[t] = b1[t] - s1 * m1[t];
        float s2 = g2[t] * rsqrtf(v2[t] + CEPS);
        g_bias2[t] = b2[t] - s2 * m2[t];
        float sr1 = gr1[t] * rsqrtf(vr1[t] + CEPS);
        g_biasr1[t] = br1[t] - sr1 * mr1[t];
        float sr2 = gr2[t] * rsqrtf(vr2[t] + CEPS);
        g_biasr2[t] = br2[t] - sr2 * mr2[t];
        float s3 = gr3[0] * rsqrtf(vr3[0] + CEPS);
        g_wr3[t] = wr3[t] * s3;
        if (t == 0) g_bias3s[0] = br3[0] - s3 * mr3[0];
    }
}

// ======================= K0b: per-fj-row column sums =======================
__global__ __launch_bounds__(128) void a0_kernel() {
    int nb = 200 + blockIdx.x;
    int o = threadIdx.x;
    int s = nb * 256;
    int rem = s % 400;
    int g0 = 400 - rem; if (g0 > 256) g0 = 256;
    float a0 = 0.f, a1 = 0.f;
    for (int cp = 0; cp < 256; cp++) {
        float w = g_wr1ft[cp * CC + o];
        if (cp < g0) a0 += w; else a1 += w;
    }
    g_A0[blockIdx.x * CC + o] = a0;
    g_A1[blockIdx.x * CC + o] = a1;
}

// ======================= K1: feat =======================
__global__ __launch_bounds__(128) void feat_kernel(const float* __restrict__ x) {
    __shared__ float xs[CC];
    int bj = blockIdx.x;
    int b = bj / CHW; int j = bj - b * CHW;
    int c = threadIdx.x;
    xs[c] = x[(b * CC + c) * CHW + j];
    __syncthreads();
    float acc = g_bias1[c];
    #pragma unroll 8
    for (int k = 0; k < CC; k++) acc += g_w1t[k * CC + c] * xs[k];
    float f = siluf(acc);
    g_feat[bj * CC + c] = f;
    g_featT[(b * CC + c) * CHW + j] = f;
}

// ======================= K2: fi rows (8 rows per CTA) =======================
// dyn smem layout (bytes):
#define FI_GST   0                  // [256 cp][8 r] floats = 8192
#define FI_PARTA 8192               // [8 r][128 o] = 4096
#define FI_R1T   12288              // [128 oo][8 r] = 4096
#define FI_REDW  16384              // [72][129] = 37152
#define FI_SVAL  53536              // 72 floats = 288
#define FI_SMEM  53824

__global__ __launch_bounds__(256) void relation_fi_kernel() {
    extern __shared__ char fsm[];
    float* gsT  = (float*)(fsm + FI_GST);
    float* partA = (float*)(fsm + FI_PARTA);
    float* r1sT = (float*)(fsm + FI_R1T);
    float* redw = (float*)(fsm + FI_REDW);
    float* sval = (float*)(fsm + FI_SVAL);

    int bg = blockIdx.x;            // 0..49
    int b = bg / 25; int g = bg - b * 25;
    int t = threadIdx.x;
    int o = t & 127; int hb = t >> 7;

    // 8 consecutive fi rows nb = g*8+r; their 256-slices are contiguous in featT
    const float* srcbase = g_featT + b * (CC * CHW) + g * 2048;
    for (int i = t; i < 2048; i += 256)
        gsT[(i & 255) * 8 + (i >> 8)] = srcbase[i];
    __syncthreads();

    // phase A: r1[r][o] = silu( sum_cp wr1ft[cp][o] * gs[r][cp] + biasr1[o] )
    float accA[8];
    float binit = hb ? 0.f : g_biasr1[o];
    #pragma unroll
    for (int r = 0; r < 8; r++) accA[r] = binit;
    int cp0 = hb * 128;
    #pragma unroll 4
    for (int cp = cp0; cp < cp0 + 128; cp++) {
        float w = g_wr1ft[cp * CC + o];
        const float4* gp = (const float4*)&gsT[cp * 8];
        float4 ga = gp[0], gb = gp[1];
        accA[0] = fmaf(w, ga.x, accA[0]);
        accA[1] = fmaf(w, ga.y, accA[1]);
        accA[2] = fmaf(w, ga.z, accA[2]);
        accA[3] = fmaf(w, ga.w, accA[3]);
        accA[4] = fmaf(w, gb.x, accA[4]);
        accA[5] = fmaf(w, gb.y, accA[5]);
        accA[6] = fmaf(w, gb.z, accA[6]);
        accA[7] = fmaf(w, gb.w, accA[7]);
    }
    if (hb) {
        #pragma unroll
        for (int r = 0; r < 8; r++) partA[r * 128 + o] = accA[r];
    }
    __syncthreads();
    if (!hb) {
        #pragma unroll
        for (int r = 0; r < 8; r++)
            r1sT[o * 8 + r] = siluf(accA[r] + partA[r * 128 + o]);
    }
    __syncthreads();

    // phase B: acc9[cls][r][o] = sum_oo T[cls][oo][o] * r1[r][oo]
    float acc9[9][8];
    #pragma unroll
    for (int cls = 0; cls < 9; cls++)
        #pragma unroll
        for (int r = 0; r < 8; r++) acc9[cls][r] = 0.f;
    int ob = hb * 64;
    for (int oo = ob; oo < ob + 64; oo++) {
        const float4* rp = (const float4*)&r1sT[oo * 8];
        float4 ra = rp[0], rb = rp[1];
        float rv[8] = {ra.x, ra.y, ra.z, ra.w, rb.x, rb.y, rb.z, rb.w};
        #pragma unroll
        for (int cls = 0; cls < 9; cls++) {
            float tv = g_T[cls * 16384 + oo * 128 + o];
            #pragma unroll
            for (int r = 0; r < 8; r++)
                acc9[cls][r] = fmaf(tv, rv[r], acc9[cls][r]);
        }
    }
    if (hb) {
        #pragma unroll
        for (int cls = 0; cls < 9; cls++)
            #pragma unroll
            for (int r = 0; r < 8; r++)
                redw[(cls * 8 + r) * 129 + o] = acc9[cls][r];
    }
    __syncthreads();
    if (!hb) {
        float w3 = g_wr3[o];
        float br2 = g_biasr2[o];
        #pragma unroll
        for (int cls = 0; cls < 9; cls++)
            #pragma unroll
            for (int r = 0; r < 8; r++) {
                float v = acc9[cls][r] + redw[(cls * 8 + r) * 129 + o] + br2;
                redw[(cls * 8 + r) * 129 + o] = w3 * siluf(v);
            }
    }
    __syncthreads();
    if (t < 72) {
        float s = g_bias3s[0];
        for (int o2 = 0; o2 < 128; o2++) s += redw[t * 129 + o2];
        sval[t] = siluf(s);
    }
    __syncthreads();

    for (int idx = t; idx < 8 * 400; idx += 256) {
        int r = idx / 400; int j = idx - r * 400;
        int y = j / 20, xp = j - y * 20;
        int rc = (y == 0) ? 0 : (y == 19 ? 2 : 1);
        int ccl = (xp == 0) ? 0 : (xp == 19 ? 2 : 1);
        g_scores[(b * CHW + g * 8 + r) * CHW + j] = sval[(rc * 3 + ccl) * 8 + r];
    }
}

// ======================= K3: fj rows via mma.sync bf16 =======================
// pitch 272B rows (68 words ≡ 4 banks mod 32 -> conflict-free ldmatrix)
#define PITCH 272
#define OFF_A0    0
#define OFF_A1    512
#define OFF_BS    1024
#define OFF_BR2   1536
#define OFF_W3    2048
#define OFF_B3    2560
#define OFF_PART  2576                  // 512 floats
#define OFF_F0    (OFF_PART + 2048)     // 4624
#define OFF_F1    (OFF_F0 + 1600)       // 6224
#define OFF_LUT   (OFF_F1 + 1600)       // 7824, 16384 bytes
#define OFF_WST0  (OFF_LUT + 16384)     // 24208, 64*272 = 17408
#define OFF_WST1  (OFF_WST0 + 17408)    // 41616
#define OFF_R1P   (OFF_WST1 + 17408)    // 59024, 558*272 = 151776
#define FJ_SMEM   (OFF_R1P + 151776)    // 210800

__global__ __launch_bounds__(256, 1) void relation_fj_mma_kernel() {
    extern __shared__ char smem[];
    uint32_t sbase = smem_to_u32(smem);
    float* a0s  = (float*)(smem + OFF_A0);
    float* a1s  = (float*)(smem + OFF_A1);
    float* bss  = (float*)(smem + OFF_BS);
    float* br2s = (float*)(smem + OFF_BR2);
    float* w3s  = (float*)(smem + OFF_W3);
    float* b3s  = (float*)(smem + OFF_B3);
    float* part = (float*)(smem + OFF_PART);
    float* f0s  = (float*)(smem + OFF_F0);
    float* f1s  = (float*)(smem + OFF_F1);
    const float2* lutp = (const float2*)(smem + OFF_LUT);
    char* r1pb = smem + OFF_R1P;

    int bi = blockIdx.x;
    int b = bi / 200; int nbr = bi - b * 200;
    int nb = 200 + nbr;
    int t = threadIdx.x;
    int w = t >> 5;
    int lane = t & 31;

    // per-row constants
    int s = nb * 256;
    int rem = s % 400;
    int g0 = 400 - rem; if (g0 > 256) g0 = 256;
    int cc0 = s / 400 - 128;
    int cc1 = (g0 < 256) ? (cc0 + 1) : cc0;

    if (t < CC) {
        a0s[t] = g_A0[nbr * CC + t];
        a1s[t] = g_A1[nbr * CC + t];
        bss[t] = g_biasr1[t];
        br2s[t] = g_biasr2[t];
        w3s[t] = g_wr3[t];
        if (t == 0) b3s[0] = g_bias3s[0];
    }
    {
        const float* f0p = g_featT + (b * CC + cc0) * CHW;
        const float* f1p = g_featT + (b * CC + cc1) * CHW;
        for (int j = t; j < CHW; j += 256) { f0s[j] = f0p[j]; f1s[j] = f1p[j]; }
    }
    for (int i = t; i < 2048; i += 256)
        ((float2*)(smem + OFF_LUT))[i] = g_lut[i];

    // zero r1p (incl. pad bytes)
    for (int i = t; i < (558 * PITCH) / 16; i += 256)
        ((uint4*)r1pb)[i] = make_uint4(0, 0, 0, 0);
    __syncthreads();

    // phase 1: interior fill r1[u=23+q][c] = silu(a0*f0 + a1*f1 + b), bf16 pairs
    for (int idx = t; idx < 400 * 64; idx += 256) {
        int j = idx >> 6, cp = idx & 63; int c = cp * 2;
        int y = j / 20, xx = j - y * 20;
        int u = 23 + (y + 1) * 22 + (xx + 1);
        float f0 = f0s[j], f1 = f1s[j];
        float t0 = fmaf(a0s[c], f0, fmaf(a1s[c], f1, bss[c]));
        float t1 = fmaf(a0s[c + 1], f0, fmaf(a1s[c + 1], f1, bss[c + 1]));
        __nv_bfloat162 h2 = __floats2bfloat162_rn(lut_silu(lutp, t0), lut_silu(lutp, t1));
        *(unsigned*)(r1pb + u * PITCH + cp * 4) = *(unsigned*)&h2;
    }

    // fragment address components
    int lrow = lane & 15;            // A row within m16
    int lcol = lane >> 4;            // A 16B col half
    int brow = (lane & 7) + ((lane >> 4) << 3);   // B row (n) within 16
    int bcol = ((lane >> 3) & 1) * 16;            // B 16B col half
    uint32_t r1addr = sbase + OFF_R1P;

    float bias3 = 0.f;

    for (int npass = 0; npass < 2; npass++) {
        float acc[4][8][4];
        #pragma unroll
        for (int mf = 0; mf < 4; mf++)
            #pragma unroll
            for (int nf = 0; nf < 8; nf++)
                #pragma unroll
                for (int q = 0; q < 4; q++) acc[mf][nf][q] = 0.f;

        // preload tap 0 W half into regs
        uint4 wreg[4];
        {
            const uint4* wsrc = (const uint4*)(g_wcv + (0 * CC + npass * 64) * CC);
            #pragma unroll
            for (int q = 0; q < 4; q++) wreg[q] = wsrc[t + q * 256];
        }

        for (int tap = 0; tap < 9; tap++) {
            char* wb = smem + ((tap & 1) ? OFF_WST1 : OFF_WST0);
            // store prefetched W into this tap's buffer
            #pragma unroll
            for (int q = 0; q < 4; q++) {
                int idx = t + q * 256;
                int r = idx >> 4, ch16 = idx & 15;
                *(uint4*)(wb + r * PITCH + ch16 * 16) = wreg[q];
            }
            // issue prefetch for next tap (overlaps barrier + MMAs)
            if (tap < 8) {
                const uint4* wsrc = (const uint4*)(g_wcv + ((tap + 1) * CC + npass * 64) * CC);
                #pragma unroll
                for (int q = 0; q < 4; q++) wreg[q] = wsrc[t + q * 256];
            }
            __syncthreads();

            int dy = tap / 3 - 1, dx = tap - (tap / 3) * 3 - 1;
            int delta = dy * 22 + dx;
            uint32_t abase = r1addr + (uint32_t)((23 + delta + w * 64 + lrow) * PITCH + lcol * 16);
            uint32_t bbase = sbase + ((tap & 1) ? OFF_WST1 : OFF_WST0)
                           + (uint32_t)(brow * PITCH + bcol);

            #pragma unroll 2
            for (int k16 = 0; k16 < 8; k16++) {
                unsigned af[4][4], bf[4][4];
                #pragma unroll
                for (int mf = 0; mf < 4; mf++)
                    ldsm_x4(af[mf], abase + mf * 16 * PITCH + k16 * 32);
                #pragma unroll
                for (int ng = 0; ng < 4; ng++)
                    ldsm_x4(bf[ng], bbase + ng * 16 * PITCH + k16 * 32);
                #pragma unroll
                for (int mf = 0; mf < 4; mf++)
                    #pragma unroll
                    for (int nf = 0; nf < 8; nf++)
                        mma16816(acc[mf][nf], af[mf], &bf[nf >> 1][(nf & 1) * 2]);
            }
        }

        // epilogue: +bias -> silu -> *w3 -> reduce over n
        if (npass == 1) bias3 = b3s[0];
        float rs[4][2];
        #pragma unroll
        for (int mf = 0; mf < 4; mf++) { rs[mf][0] = 0.f; rs[mf][1] = 0.f; }
        #pragma unroll
        for (int nf = 0; nf < 8; nf++) {
            int c2 = npass * 64 + nf * 8 + (lane & 3) * 2;
            float wa = w3s[c2], wb2 = w3s[c2 + 1];
            float ba = br2s[c2], bb = br2s[c2 + 1];
            #pragma unroll
            for (int mf = 0; mf < 4; mf++) {
                rs[mf][0] += wa * lut_silu(lutp, acc[mf][nf][0] + ba)
                           + wb2 * lut_silu(lutp, acc[mf][nf][1] + bb);
                rs[mf][1] += wa * lut_silu(lutp, acc[mf][nf][2] + ba)
                           + wb2 * lut_silu(lutp, acc[mf][nf][3] + bb);
            }
        }
        #pragma unroll
        for (int mf = 0; mf < 4; mf++) {
            #pragma unroll
            for (int h = 0; h < 2; h++) {
                float v = rs[mf][h];
                v += __shfl_xor_sync(0xFFFFFFFF, v, 1);
                v += __shfl_xor_sync(0xFFFFFFFF, v, 2);
                if ((lane & 3) == 0) {
                    int m0 = w * 64 + mf * 16 + (lane >> 2) + h * 8;
                    if (npass == 0) {
                        part[m0] = v;
                    } else {
                        if (m0 < 484) {
                            int y = m0 / 22, xx = m0 - y * 22;
                            if (y >= 1 && y < 21 && xx >= 1 && xx < 21) {
                                int p = (y - 1) * 20 + (xx - 1);
                                float sc = bias3 + part[m0] + v;
                                g_scores[(b * CHW + nb) * CHW + p] = lut_silu(lutp, sc);
                            }
                        }
                    }
                }
            }
        }
        // make W buffers + part[] safe for next npass
        __syncthreads();
    }
}

// ======================= K4: att + CBS2 + residual =======================
__global__ __launch_bounds__(128) void att_kernel(const float* __restrict__ x,
                                                  float* __restrict__ out) {
    __shared__ float sc[CHW];
    __shared__ float at[CC];
    int bi = blockIdx.x;
    int b = bi / CHW; int i = bi - b * CHW;
    int t = threadIdx.x;
    for (int j = t; j < CHW; j += 128) sc[j] = g_scores[bi * CHW + j];
    __syncthreads();
    float acc = 0.f;
    const float* fb = g_feat + b * CHW * CC;
    #pragma unroll 4
    for (int j = 0; j < CHW; j++) acc += sc[j] * fb[j * CC + t];
    at[t] = acc;
    __syncthreads();
    float o = g_bias2[t];
    #pragma unroll 8
    for (int k = 0; k < CC; k++) o += g_w2t[k * CC + t] * at[k];
    int oi = (b * CC + t) * CHW + i;
    out[oi] = siluf(o) + x[oi];
}

// ======================= launch =======================
extern "C" void kernel_launch(void* const* d_in, const int* in_sizes, int n_in,
                              void* d_out, int out_size) {
    (void)in_sizes; (void)n_in; (void)out_size;
    Params P;
    for (int i = 0; i < 26; i++) P.p[i] = (const float*)d_in[i];
    const float* x = (const float*)d_in[0];
    float* out = (float*)d_out;

    fold_kernel<<<64, 256>>>(P);
    a0_kernel<<<200, 128>>>();
    feat_kernel<<<CB * CHW, 128>>>(x);

    cudaFuncSetAttribute(relation_fi_kernel,
                         cudaFuncAttributeMaxDynamicSharedMemorySize, FI_SMEM);
    relation_fi_kernel<<<CB * 25, 256, FI_SMEM>>>();

    cudaFuncSetAttribute(relation_fj_mma_kernel,
                         cudaFuncAttributeMaxDynamicSharedMemorySize, FJ_SMEM);
    relation_fj_mma_kernel<<<CB * 200, 256, FJ_SMEM>>>();

    att_kernel<<<CB * CHW, 128>>>(x, out);
}

// round 7
// speedup vs baseline: 1.0738x; 1.0738x over previous
#include <cuda_runtime.h>
#include <cuda_bf16.h>
#include <cstdint>

#define CB   2
#define CC   128
#define CH   20
#define CW   20
#define CHW  400
#define CEPS 1e-5f

// ======================= helpers =======================
__device__ __forceinline__ uint32_t smem_to_u32(const void* p) {
    uint32_t a;
    asm("{ .reg .u64 t; cvta.to.shared.u64 t, %1; cvt.u32.u64 %0, t; }" : "=r"(a) : "l"(p));
    return a;
}
__device__ __forceinline__ void ldsm_x4(unsigned* r, uint32_t addr) {
    asm volatile("ldmatrix.sync.aligned.m8n8.x4.shared.b16 {%0,%1,%2,%3}, [%4];"
        : "=r"(r[0]), "=r"(r[1]), "=r"(r[2]), "=r"(r[3]) : "r"(addr));
}
__device__ __forceinline__ void mma16816(float* d, const unsigned* a, const unsigned* b) {
    asm volatile("mma.sync.aligned.m16n8k16.row.col.f32.bf16.bf16.f32 "
        "{%0,%1,%2,%3}, {%4,%5,%6,%7}, {%8,%9}, {%0,%1,%2,%3};"
        : "+f"(d[0]), "+f"(d[1]), "+f"(d[2]), "+f"(d[3])
        : "r"(a[0]), "r"(a[1]), "r"(a[2]), "r"(a[3]), "r"(b[0]), "r"(b[1]));
}

// ======================= device scratch =======================
__device__ float g_w1t[CC * CC];
__device__ float g_bias1[CC];
__device__ float g_w2t[CC * CC];
__device__ float g_bias2[CC];
__device__ float g_wr1ft[256 * CC];
__device__ float g_biasr1[CC];
__device__ float g_T[9 * CC * CC];
__device__ float g_biasr2[CC];
__device__ float g_wr3[CC];
__device__ float g_bias3s[1];
__device__ float g_A0[200 * CC];
__device__ float g_A1[200 * CC];
__device__ float g_feat[CB * CHW * CC];
__device__ float g_featT[CB * CC * CHW];
__device__ float g_scores[CB * CHW * CHW];
__device__ __align__(16) __nv_bfloat16 g_wcv[9 * CC * CC]; // [tap][c2][ch] folded bf16
__device__ float2 g_lut[2048];

struct Params { const float* p[26]; };

__device__ __forceinline__ float siluf(float x) {
    float s = 1.f / (1.f + __expf(-x));
    return x * s;
}
__device__ __forceinline__ float lut_silu(const float2* lut, float x) {
    float xc = fminf(fmaxf(x, -16.0f), 15.99993f);
    float fi = (xc + 16.0f) * 64.0f;
    int i = (int)fi;
    float fr = fi - (float)i;
    float2 e = lut[i];
    float y = fmaf(fr, e.y, e.x);
    return (x >= 16.0f) ? x : y;
}

// ======================= K0: fold =======================
__global__ void fold_kernel(Params P) {
    const float* w1  = P.p[1];
    const float* g1  = P.p[2];  const float* b1 = P.p[3];
    const float* m1  = P.p[4];  const float* v1 = P.p[5];
    const float* w2  = P.p[6];
    const float* g2  = P.p[7];  const float* b2 = P.p[8];
    const float* m2  = P.p[9];  const float* v2 = P.p[10];
    const float* wr1 = P.p[11];
    const float* gr1 = P.p[12]; const float* br1 = P.p[13];
    const float* mr1 = P.p[14]; const float* vr1 = P.p[15];
    const float* wr2 = P.p[16];
    const float* gr2 = P.p[17]; const float* br2 = P.p[18];
    const float* mr2 = P.p[19]; const float* vr2 = P.p[20];
    const float* wr3 = P.p[21];
    const float* gr3 = P.p[22]; const float* br3 = P.p[23];
    const float* mr3 = P.p[24]; const float* vr3 = P.p[25];

    int t = blockIdx.x * blockDim.x + threadIdx.x;
    int stride = gridDim.x * blockDim.x;

    for (int i = t; i < CC * CC; i += stride) {
        int c = i >> 7, k = i & 127;
        float s  = g1[c] * rsqrtf(v1[c] + CEPS);
        g_w1t[k * CC + c] = w1[i] * s;
        float s2 = g2[c] * rsqrtf(v2[c] + CEPS);
        g_w2t[k * CC + c] = w2[i] * s2;
    }
    for (int i = t; i < 256 * CC; i += stride) {
        int cp = i >> 7, o = i & 127;
        float sr = gr1[o] * rsqrtf(vr1[o] + CEPS);
        g_wr1ft[cp * CC + o] = wr1[o * 256 + cp] * sr;
    }
    // conv weights bf16 [tap][c2][ch]
    for (int i = t; i < 9 * CC * CC; i += stride) {
        int di = i >> 14; int r = i & 16383;
        int c2 = r >> 7; int c = r & 127;
        float s = gr2[c2] * rsqrtf(vr2[c2] + CEPS);
        g_wcv[i] = __float2bfloat16(wr2[(c2 * CC + c) * 9 + di] * s);
    }
    // silu LUT
    for (int i = t; i < 2048; i += stride) {
        float x0 = -16.0f + (float)i * 0.015625f;
        float x1 = x0 + 0.015625f;
        float s0 = x0 / (1.0f + expf(-x0));
        float s1 = x1 / (1.0f + expf(-x1));
        g_lut[i] = make_float2(s0, s1 - s0);
    }
    // border-class tap sums for fi path
    for (int i = t; i < 9 * CC * CC; i += stride) {
        int cls = i >> 14; int r = i & 16383;
        int o = r >> 7; int o2 = r & 127;
        int rc = cls / 3, ccl = cls - rc * 3;
        float s = gr2[o2] * rsqrtf(vr2[o2] + CEPS);
        float acc = 0.f;
        #pragma unroll
        for (int k = 0; k < 9; k++) {
            int ky = k / 3, kx = k - ky * 3;
            bool rok = (rc == 1) || (rc == 0 ? (ky >= 1) : (ky <= 1));
            bool cok = (ccl == 1) || (ccl == 0 ? (kx >= 1) : (kx <= 1));
            if (rok && cok) acc += wr2[(o2 * CC + o) * 9 + k];
        }
        g_T[i] = acc * s;
    }
    if (t < CC) {
        float s1 = g1[t] * rsqrtf(v1[t] + CEPS);
        g_bias1[t] = b1[t] - s1 * m1[t];
        float s2 = g2[t] * rsqrtf(v2[t] + CEPS);
        g_bias2[t] = b2[t] - s2 * m2[t];
        float sr1 = gr1[t] * rsqrtf(vr1[t] + CEPS);
        g_biasr1[t] = br1[t] - sr1 * mr1[t];
        float sr2 = gr2[t] * rsqrtf(vr2[t] + CEPS);
        g_biasr2[t] = br2[t] - sr2 * mr2[t];
        float s3 = gr3[0] * rsqrtf(vr3[0] + CEPS);
        g_wr3[t] = wr3[t] * s3;
        if (t == 0) g_bias3s[0] = br3[0] - s3 * mr3[0];
    }
}

// ======================= K0b: per-fj-row column sums =======================
__global__ __launch_bounds__(128) void a0_kernel() {
    int nb = 200 + blockIdx.x;
    int o = threadIdx.x;
    int s = nb * 256;
    int rem = s % 400;
    int g0 = 400 - rem; if (g0 > 256) g0 = 256;
    float a0 = 0.f, a1 = 0.f;
    for (int cp = 0; cp < 256; cp++) {
        float w = g_wr1ft[cp * CC + o];
        if (cp < g0) a0 += w; else a1 += w;
    }
    g_A0[blockIdx.x * CC + o] = a0;
    g_A1[blockIdx.x * CC + o] = a1;
}

// ======================= K1: feat (4 pixels/CTA) =======================
__global__ __launch_bounds__(128) void feat_kernel(const float* __restrict__ x) {
    __shared__ float4 xs4[CC];
    int bg = blockIdx.x;
    int b = bg / 100; int g = bg - b * 100;   // pixels j = 4g..4g+3
    int c = threadIdx.x;
    xs4[c] = *(const float4*)&x[(b * CC + c) * CHW + g * 4];
    __syncthreads();
    float a0 = g_bias1[c], a1 = a0, a2 = a0, a3 = a0;
    #pragma unroll 4
    for (int k = 0; k < CC; k++) {
        float w = g_w1t[k * CC + c];
        float4 xv = xs4[k];
        a0 = fmaf(w, xv.x, a0);
        a1 = fmaf(w, xv.y, a1);
        a2 = fmaf(w, xv.z, a2);
        a3 = fmaf(w, xv.w, a3);
    }
    float f0 = siluf(a0), f1 = siluf(a1), f2 = siluf(a2), f3 = siluf(a3);
    int j0 = g * 4;
    g_feat[(b * CHW + j0 + 0) * CC + c] = f0;
    g_feat[(b * CHW + j0 + 1) * CC + c] = f1;
    g_feat[(b * CHW + j0 + 2) * CC + c] = f2;
    g_feat[(b * CHW + j0 + 3) * CC + c] = f3;
    *(float4*)&g_featT[(b * CC + c) * CHW + j0] = make_float4(f0, f1, f2, f3);
}

// ======================= K2: fi rows (2 rows/CTA, grid 200) ================
#define FI2_GS    0                 // gs[2][256] = 2048 B
#define FI2_PART  2048              // partA[2][128] = 1024
#define FI2_R1T   3072              // r1T[128][2] = 1024
#define FI2_REDQ  4096              // redq[4][2304] = 36864
#define FI2_REDS  40960             // redsum[2304] = 9216
#define FI2_SVAL  50176             // 18 floats
#define FI2_SMEM  50304

__global__ __launch_bounds__(256) void relation_fi_kernel() {
    extern __shared__ char fsm[];
    float* gs     = (float*)(fsm + FI2_GS);
    float* partA  = (float*)(fsm + FI2_PART);
    float* r1T    = (float*)(fsm + FI2_R1T);
    float* redq   = (float*)(fsm + FI2_REDQ);
    float* redsum = (float*)(fsm + FI2_REDS);
    float* sval   = (float*)(fsm + FI2_SVAL);

    int bg = blockIdx.x;               // 0..199
    int b = bg / 100; int g = bg - b * 100;   // rows nb = 2g, 2g+1
    int t = threadIdx.x;

    // load both rows' 256-slices (contiguous 512 floats in featT)
    const float* src = g_featT + b * (CC * CHW) + g * 512;
    gs[t] = src[t];
    gs[t + 256] = src[t + 256];
    __syncthreads();

    // phase A: r1[r][o] = silu(sum_cp wr1ft[cp][o]*gs[r][cp] + b[o]) (split halves)
    {
        int o = t & 127, hb = t >> 7;
        float acc0 = hb ? 0.f : g_biasr1[o];
        float acc1 = acc0;
        int cp0 = hb * 128;
        #pragma unroll 4
        for (int cp = cp0; cp < cp0 + 128; cp++) {
            float w = g_wr1ft[cp * CC + o];
            acc0 = fmaf(w, gs[cp], acc0);
            acc1 = fmaf(w, gs[256 + cp], acc1);
        }
        if (hb) { partA[o] = acc0; partA[128 + o] = acc1; }
        __syncthreads();
        if (!hb) {
            r1T[o * 2 + 0] = siluf(acc0 + partA[o]);
            r1T[o * 2 + 1] = siluf(acc1 + partA[128 + o]);
        }
    }
    __syncthreads();

    // phase B: thread = (o-pair, oo-quarter); float2 T loads, 4 FMA each
    {
        int op = t & 63, q = t >> 6;
        int o0 = op * 2;
        float acc[9][4];
        #pragma unroll
        for (int cls = 0; cls < 9; cls++)
            #pragma unroll
            for (int z = 0; z < 4; z++) acc[cls][z] = 0.f;
        int oos = q * 32;
        for (int oo = oos; oo < oos + 32; oo++) {
            float2 rv = *(float2*)&r1T[oo * 2];
            #pragma unroll
            for (int cls = 0; cls < 9; cls++) {
                float2 tv = *(const float2*)&g_T[cls * 16384 + oo * 128 + o0];
                acc[cls][0] = fmaf(tv.x, rv.x, acc[cls][0]);
                acc[cls][1] = fmaf(tv.y, rv.x, acc[cls][1]);
                acc[cls][2] = fmaf(tv.x, rv.y, acc[cls][2]);
                acc[cls][3] = fmaf(tv.y, rv.y, acc[cls][3]);
            }
        }
        float* rq = redq + q * 2304;
        #pragma unroll
        for (int cls = 0; cls < 9; cls++) {
            *(float2*)&rq[(cls * 2 + 0) * 128 + o0] = make_float2(acc[cls][0], acc[cls][1]);
            *(float2*)&rq[(cls * 2 + 1) * 128 + o0] = make_float2(acc[cls][2], acc[cls][3]);
        }
    }
    __syncthreads();

    // combine quarters + bias + silu + *w3
    for (int item = t; item < 2304; item += 256) {
        float v = redq[item] + redq[2304 + item] + redq[4608 + item] + redq[6912 + item];
        int o = item & 127;
        redsum[item] = g_wr3[o] * siluf(v + g_biasr2[o]);
    }
    __syncthreads();
    if (t < 18) {
        float s = g_bias3s[0];
        for (int o = 0; o < 128; o++) s += redsum[t * 128 + o];
        sval[t] = siluf(s);
    }
    __syncthreads();

    for (int idx = t; idx < 800; idx += 256) {
        int r = idx / 400; int j = idx - r * 400;
        int y = j / 20, xp = j - y * 20;
        int rc = (y == 0) ? 0 : (y == 19 ? 2 : 1);
        int ccl = (xp == 0) ? 0 : (xp == 19 ? 2 : 1);
        g_scores[(b * CHW + g * 2 + r) * CHW + j] = sval[(rc * 3 + ccl) * 2 + r];
    }
}

// ======================= K3: fj rows via mma.sync bf16 =======================
// pitch 272B rows (68 words ≡ 4 banks mod 32 -> conflict-free ldmatrix)
#define PITCH 272
#define OFF_A0    0
#define OFF_A1    512
#define OFF_BS    1024
#define OFF_BR2   1536
#define OFF_W3    2048
#define OFF_B3    2560
#define OFF_PART  2576                  // 512 floats
#define OFF_F0    (OFF_PART + 2048)     // 4624
#define OFF_F1    (OFF_F0 + 1600)       // 6224
#define OFF_LUT   (OFF_F1 + 1600)       // 7824, 16384 bytes
#define OFF_WST0  (OFF_LUT + 16384)     // 24208, 64*272 = 17408
#define OFF_WST1  (OFF_WST0 + 17408)    // 41616
#define OFF_R1P   (OFF_WST1 + 17408)    // 59024, 558*272 = 151776
#define FJ_SMEM   (OFF_R1P + 151776)    // 210800

__global__ __launch_bounds__(256, 1) void relation_fj_mma_kernel() {
    extern __shared__ char smem[];
    uint32_t sbase = smem_to_u32(smem);
    float* a0s  = (float*)(smem + OFF_A0);
    float* a1s  = (float*)(smem + OFF_A1);
    float* bss  = (float*)(smem + OFF_BS);
    float* br2s = (float*)(smem + OFF_BR2);
    float* w3s  = (float*)(smem + OFF_W3);
    float* b3s  = (float*)(smem + OFF_B3);
    float* part = (float*)(smem + OFF_PART);
    float* f0s  = (float*)(smem + OFF_F0);
    float* f1s  = (float*)(smem + OFF_F1);
    const float2* lutp = (const float2*)(smem + OFF_LUT);
    char* r1pb = smem + OFF_R1P;

    int bi = blockIdx.x;
    int b = bi / 200; int nbr = bi - b * 200;
    int nb = 200 + nbr;
    int t = threadIdx.x;
    int w = t >> 5;
    int lane = t & 31;

    // per-row constants
    int s = nb * 256;
    int rem = s % 400;
    int g0 = 400 - rem; if (g0 > 256) g0 = 256;
    int cc0 = s / 400 - 128;
    int cc1 = (g0 < 256) ? (cc0 + 1) : cc0;

    if (t < CC) {
        a0s[t] = g_A0[nbr * CC + t];
        a1s[t] = g_A1[nbr * CC + t];
        bss[t] = g_biasr1[t];
        br2s[t] = g_biasr2[t];
        w3s[t] = g_wr3[t];
        if (t == 0) b3s[0] = g_bias3s[0];
    }
    {
        const float* f0p = g_featT + (b * CC + cc0) * CHW;
        const float* f1p = g_featT + (b * CC + cc1) * CHW;
        for (int j = t; j < CHW; j += 256) { f0s[j] = f0p[j]; f1s[j] = f1p[j]; }
    }
    for (int i = t; i < 2048; i += 256)
        ((float2*)(smem + OFF_LUT))[i] = g_lut[i];

    // zero r1p (incl. pad bytes)
    for (int i = t; i < (558 * PITCH) / 16; i += 256)
        ((uint4*)r1pb)[i] = make_uint4(0, 0, 0, 0);
    __syncthreads();

    // phase 1: interior fill r1[u=23+q][c] = silu(a0*f0 + a1*f1 + b), bf16 pairs
    for (int idx = t; idx < 400 * 64; idx += 256) {
        int j = idx >> 6, cp = idx & 63; int c = cp * 2;
        int y = j / 20, xx = j - y * 20;
        int u = 23 + (y + 1) * 22 + (xx + 1);
        float f0 = f0s[j], f1 = f1s[j];
        float t0 = fmaf(a0s[c], f0, fmaf(a1s[c], f1, bss[c]));
        float t1 = fmaf(a0s[c + 1], f0, fmaf(a1s[c + 1], f1, bss[c + 1]));
        __nv_bfloat162 h2 = __floats2bfloat162_rn(lut_silu(lutp, t0), lut_silu(lutp, t1));
        *(unsigned*)(r1pb + u * PITCH + cp * 4) = *(unsigned*)&h2;
    }

    // fragment address components
    int lrow = lane & 15;            // A row within m16
    int lcol = lane >> 4;            // A 16B col half
    int brow = (lane & 7) + ((lane >> 4) << 3);   // B row (n) within 16
    int bcol = ((lane >> 3) & 1) * 16;            // B 16B col half
    uint32_t r1addr = sbase + OFF_R1P;

    float bias3 = 0.f;

    for (int npass = 0; npass < 2; npass++) {
        float acc[4][8][4];
        #pragma unroll
        for (int mf = 0; mf < 4; mf++)
            #pragma unroll
            for (int nf = 0; nf < 8; nf++)
                #pragma unroll
                for (int q = 0; q < 4; q++) acc[mf][nf][q] = 0.f;

        // preload tap 0 W half into regs
        uint4 wreg[4];
        {
            const uint4* wsrc = (const uint4*)(g_wcv + (0 * CC + npass * 64) * CC);
            #pragma unroll
            for (int q = 0; q < 4; q++) wreg[q] = wsrc[t + q * 256];
        }

        for (int tap = 0; tap < 9; tap++) {
            char* wb = smem + ((tap & 1) ? OFF_WST1 : OFF_WST0);
            // store prefetched W into this tap's buffer
            #pragma unroll
            for (int q = 0; q < 4; q++) {
                int idx = t + q * 256;
                int r = idx >> 4, ch16 = idx & 15;
                *(uint4*)(wb + r * PITCH + ch16 * 16) = wreg[q];
            }
            // issue prefetch for next tap (overlaps barrier + MMAs)
            if (tap < 8) {
                const uint4* wsrc = (const uint4*)(g_wcv + ((tap + 1) * CC + npass * 64) * CC);
                #pragma unroll
                for (int q = 0; q < 4; q++) wreg[q] = wsrc[t + q * 256];
            }
            __syncthreads();

            int dy = tap / 3 - 1, dx = tap - (tap / 3) * 3 - 1;
            int delta = dy * 22 + dx;
            uint32_t abase = r1addr + (uint32_t)((23 + delta + w * 64 + lrow) * PITCH + lcol * 16);
            uint32_t bbase = sbase + ((tap & 1) ? OFF_WST1 : OFF_WST0)
                           + (uint32_t)(brow * PITCH + bcol);

            #pragma unroll 2
            for (int k16 = 0; k16 < 8; k16++) {
                unsigned af[4][4], bf[4][4];
                #pragma unroll
                for (int mf = 0; mf < 4; mf++)
                    ldsm_x4(af[mf], abase + mf * 16 * PITCH + k16 * 32);
                #pragma unroll
                for (int ng = 0; ng < 4; ng++)
                    ldsm_x4(bf[ng], bbase + ng * 16 * PITCH + k16 * 32);
                #pragma unroll
                for (int mf = 0; mf < 4; mf++)
                    #pragma unroll
                    for (int nf = 0; nf < 8; nf++)
                        mma16816(acc[mf][nf], af[mf], &bf[nf >> 1][(nf & 1) * 2]);
            }
        }

        // epilogue: +bias -> silu -> *w3 -> reduce over n
        if (npass == 1) bias3 = b3s[0];
        float rs[4][2];
        #pragma unroll
        for (int mf = 0; mf < 4; mf++) { rs[mf][0] = 0.f; rs[mf][1] = 0.f; }
        #pragma unroll
        for (int nf = 0; nf < 8; nf++) {
            int c2 = npass * 64 + nf * 8 + (lane & 3) * 2;
            float wa = w3s[c2], wb2 = w3s[c2 + 1];
            float ba = br2s[c2], bb = br2s[c2 + 1];
            #pragma unroll
            for (int mf = 0; mf < 4; mf++) {
                rs[mf][0] += wa * lut_silu(lutp, acc[mf][nf][0] + ba)
                           + wb2 * lut_silu(lutp, acc[mf][nf][1] + bb);
                rs[mf][1] += wa * lut_silu(lutp, acc[mf][nf][2] + ba)
                           + wb2 * lut_silu(lutp, acc[mf][nf][3] + bb);
            }
        }
        #pragma unroll
        for (int mf = 0; mf < 4; mf++) {
            #pragma unroll
            for (int h = 0; h < 2; h++) {
                float v = rs[mf][h];
                v += __shfl_xor_sync(0xFFFFFFFF, v, 1);
                v += __shfl_xor_sync(0xFFFFFFFF, v, 2);
                if ((lane & 3) == 0) {
                    int m0 = w * 64 + mf * 16 + (lane >> 2) + h * 8;
                    if (npass == 0) {
                        part[m0] = v;
                    } else {
                        if (m0 < 484) {
                            int y = m0 / 22, xx = m0 - y * 22;
                            if (y >= 1 && y < 21 && xx >= 1 && xx < 21) {
                                int p = (y - 1) * 20 + (xx - 1);
                                float sc = bias3 + part[m0] + v;
                                g_scores[(b * CHW + nb) * CHW + p] = lut_silu(lutp, sc);
                            }
                        }
                    }
                }
            }
        }
        // make W buffers + part[] safe for next npass
        __syncthreads();
    }
}

// ======================= K4: att (4 rows/CTA) + CBS2 + residual ============
__global__ __launch_bounds__(128) void att_kernel(const float* __restrict__ x,
                                                  float* __restrict__ out) {
    __shared__ float sc[4][CHW];
    __shared__ float at[4][CC];
    int bg = blockIdx.x;
    int b = bg / 100; int g = bg - b * 100;   // rows i = 4g..4g+3
    int t = threadIdx.x;
    const float* srow = g_scores + (b * CHW + g * 4) * CHW;
    for (int idx = t; idx < 4 * CHW; idx += 128) {
        int r = idx / CHW;
        sc[r][idx - r * CHW] = srow[idx];
    }
    __syncthreads();
    float a0 = 0.f, a1 = 0.f, a2 = 0.f, a3 = 0.f;
    const float* fb = g_feat + b * CHW * CC;
    #pragma unroll 4
    for (int j = 0; j < CHW; j++) {
        float fv = fb[j * CC + t];
        a0 = fmaf(sc[0][j], fv, a0);
        a1 = fmaf(sc[1][j], fv, a1);
        a2 = fmaf(sc[2][j], fv, a2);
        a3 = fmaf(sc[3][j], fv, a3);
    }
    at[0][t] = a0; at[1][t] = a1; at[2][t] = a2; at[3][t] = a3;
    __syncthreads();
    float o0 = g_bias2[t], o1 = o0, o2 = o0, o3 = o0;
    #pragma unroll 4
    for (int k = 0; k < CC; k++) {
        float w = g_w2t[k * CC + t];
        o0 = fmaf(w, at[0][k], o0);
        o1 = fmaf(w, at[1][k], o1);
        o2 = fmaf(w, at[2][k], o2);
        o3 = fmaf(w, at[3][k], o3);
    }
    int obase = (b * CC + t) * CHW + g * 4;
    float4 xv = *(const float4*)&x[obase];
    float4 ov = make_float4(siluf(o0) + xv.x, siluf(o1) + xv.y,
                            siluf(o2) + xv.z, siluf(o3) + xv.w);
    *(float4*)&out[obase] = ov;
}

// ======================= launch =======================
extern "C" void kernel_launch(void* const* d_in, const int* in_sizes, int n_in,
                              void* d_out, int out_size) {
    (void)in_sizes; (void)n_in; (void)out_size;
    Params P;
    for (int i = 0; i < 26; i++) P.p[i] = (const float*)d_in[i];
    const float* x = (const float*)d_in[0];
    float* out = (float*)d_out;

    fold_kernel<<<64, 256>>>(P);
    a0_kernel<<<200, 128>>>();
    feat_kernel<<<CB * 100, 128>>>(x);

    cudaFuncSetAttribute(relation_fi_kernel,
                         cudaFuncAttributeMaxDynamicSharedMemorySize, FI2_SMEM);
    relation_fi_kernel<<<CB * 100, 256, FI2_SMEM>>>();

    cudaFuncSetAttribute(relation_fj_mma_kernel,
                         cudaFuncAttributeMaxDynamicSharedMemorySize, FJ_SMEM);
    relation_fj_mma_kernel<<<CB * 200, 256, FJ_SMEM>>>();

    att_kernel<<<CB * 100, 128>>>(x, out);
}

// round 9
// speedup vs baseline: 1.1209x; 1.0439x over previous
#include <cuda_runtime.h>
#include <cuda_bf16.h>
#include <cstdint>

#define CB   2
#define CC   128
#define CH   20
#define CW   20
#define CHW  400
#define CEPS 1e-5f

// ======================= helpers =======================
__device__ __forceinline__ uint32_t smem_to_u32(const void* p) {
    uint32_t a;
    asm("{ .reg .u64 t; cvta.to.shared.u64 t, %1; cvt.u32.u64 %0, t; }" : "=r"(a) : "l"(p));
    return a;
}
__device__ __forceinline__ void ldsm_x4(unsigned* r, uint32_t addr) {
    asm volatile("ldmatrix.sync.aligned.m8n8.x4.shared.b16 {%0,%1,%2,%3}, [%4];"
        : "=r"(r[0]), "=r"(r[1]), "=r"(r[2]), "=r"(r[3]) : "r"(addr));
}
__device__ __forceinline__ void mma16816(float* d, const unsigned* a, const unsigned* b) {
    asm volatile("mma.sync.aligned.m16n8k16.row.col.f32.bf16.bf16.f32 "
        "{%0,%1,%2,%3}, {%4,%5,%6,%7}, {%8,%9}, {%0,%1,%2,%3};"
        : "+f"(d[0]), "+f"(d[1]), "+f"(d[2]), "+f"(d[3])
        : "r"(a[0]), "r"(a[1]), "r"(a[2]), "r"(a[3]), "r"(b[0]), "r"(b[1]));
}
__device__ __forceinline__ void cp_async16(uint32_t daddr, const void* src) {
    asm volatile("cp.async.cg.shared.global [%0], [%1], 16;" :: "r"(daddr), "l"(src) : "memory");
}
#define CP_COMMIT() asm volatile("cp.async.commit_group;" ::: "memory")
#define CP_WAIT1()  asm volatile("cp.async.wait_group 1;" ::: "memory")
#define CP_WAIT0()  asm volatile("cp.async.wait_group 0;" ::: "memory")

// ======================= device scratch =======================
__device__ float g_w1t[CC * CC];
__device__ float g_bias1[CC];
__device__ float g_w2t[CC * CC];
__device__ float g_bias2[CC];
__device__ float g_wr1ft[256 * CC];
__device__ float g_biasr1[CC];
__device__ __align__(16) float g_T[9 * CC * CC];   // [cls][o(oo)][o2]
__device__ float g_biasr2[CC];
__device__ float g_wr3[CC];
__device__ float g_bias3s[1];
__device__ float g_A0[200 * CC];
__device__ float g_A1[200 * CC];
__device__ float g_feat[CB * CHW * CC];
__device__ float g_featT[CB * CC * CHW];
__device__ float g_scores[CB * CHW * CHW];
__device__ __align__(16) __nv_bfloat16 g_wcv[9 * CC * CC]; // [tap][c2][ch] folded bf16
__device__ float2 g_lut[2048];

struct Params { const float* p[26]; };

__device__ __forceinline__ float siluf(float x) {
    float s = 1.f / (1.f + __expf(-x));
    return x * s;
}
__device__ __forceinline__ float lut_silu(const float2* lut, float x) {
    float xc = fminf(fmaxf(x, -16.0f), 15.99993f);
    float fi = (xc + 16.0f) * 64.0f;
    int i = (int)fi;
    float fr = fi - (float)i;
    float2 e = lut[i];
    float y = fmaf(fr, e.y, e.x);
    return (x >= 16.0f) ? x : y;
}

// ======================= K0: fold (no g_T here anymore) =======================
__global__ void fold_kernel(Params P) {
    const float* w1  = P.p[1];
    const float* g1  = P.p[2];  const float* b1 = P.p[3];
    const float* m1  = P.p[4];  const float* v1 = P.p[5];
    const float* w2  = P.p[6];
    const float* g2  = P.p[7];  const float* b2 = P.p[8];
    const float* m2  = P.p[9];  const float* v2 = P.p[10];
    const float* wr1 = P.p[11];
    const float* gr1 = P.p[12]; const float* br1 = P.p[13];
    const float* mr1 = P.p[14]; const float* vr1 = P.p[15];
    const float* wr2 = P.p[16];
    const float* gr2 = P.p[17]; const float* br2 = P.p[18];
    const float* mr2 = P.p[19]; const float* vr2 = P.p[20];
    const float* wr3 = P.p[21];
    const float* gr3 = P.p[22]; const float* br3 = P.p[23];
    const float* mr3 = P.p[24]; const float* vr3 = P.p[25];

    int t = blockIdx.x * blockDim.x + threadIdx.x;
    int stride = gridDim.x * blockDim.x;

    for (int i = t; i < CC * CC; i += stride) {
        int c = i >> 7, k = i & 127;
        float s  = g1[c] * rsqrtf(v1[c] + CEPS);
        g_w1t[k * CC + c] = w1[i] * s;
        float s2 = g2[c] * rsqrtf(v2[c] + CEPS);
        g_w2t[k * CC + c] = w2[i] * s2;
    }
    for (int i = t; i < 256 * CC; i += stride) {
        int cp = i >> 7, o = i & 127;
        float sr = gr1[o] * rsqrtf(vr1[o] + CEPS);
        g_wr1ft[cp * CC + o] = wr1[o * 256 + cp] * sr;
    }
    // conv weights bf16 [tap][c2][ch]
    for (int i = t; i < 9 * CC * CC; i += stride) {
        int di = i >> 14; int r = i & 16383;
        int c2 = r >> 7; int c = r & 127;
        float s = gr2[c2] * rsqrtf(vr2[c2] + CEPS);
        g_wcv[i] = __float2bfloat16(wr2[(c2 * CC + c) * 9 + di] * s);
    }
    // silu LUT
    for (int i = t; i < 2048; i += stride) {
        float x0 = -16.0f + (float)i * 0.015625f;
        float x1 = x0 + 0.015625f;
        float s0 = x0 / (1.0f + expf(-x0));
        float s1 = x1 / (1.0f + expf(-x1));
        g_lut[i] = make_float2(s0, s1 - s0);
    }
    if (t < CC) {
        float s1 = g1[t] * rsqrtf(v1[t] + CEPS);
        g_bias1[t] = b1[t] - s1 * m1[t];
        float s2 = g2[t] * rsqrtf(v2[t] + CEPS);
        g_bias2[t] = b2[t] - s2 * m2[t];
        float sr1 = gr1[t] * rsqrtf(vr1[t] + CEPS);
        g_biasr1[t] = br1[t] - sr1 * mr1[t];
        float sr2 = gr2[t] * rsqrtf(vr2[t] + CEPS);
        g_biasr2[t] = br2[t] - sr2 * mr2[t];
        float s3 = gr3[0] * rsqrtf(vr3[0] + CEPS);
        g_wr3[t] = wr3[t] * s3;
        if (t == 0) g_bias3s[0] = br3[0] - s3 * mr3[0];
    }
}

// ======================= K0t: build g_T coalesced =======================
__global__ __launch_bounds__(256) void buildT_kernel(const float* __restrict__ wr2,
                                                     const float* __restrict__ gr2,
                                                     const float* __restrict__ vr2) {
    __shared__ float W8[8 * 1152];       // 36 KB
    int chunk = blockIdx.x;              // o2 = chunk*8 + z
    int t = threadIdx.x;
    for (int i = t; i < 8 * 1152; i += 256) {
        int z = i / 1152; int r = i - z * 1152;
        int o2 = chunk * 8 + z;
        float s = gr2[o2] * rsqrtf(vr2[o2] + CEPS);
        W8[i] = wr2[o2 * 1152 + r] * s;
    }
    __syncthreads();
    for (int p = t; p < 1152; p += 256) {
        int cls = p >> 7; int o = p & 127;
        int rc = cls / 3, ccl = cls - rc * 3;
        float out[8];
        #pragma unroll
        for (int z = 0; z < 8; z++) out[z] = 0.f;
        #pragma unroll
        for (int k = 0; k < 9; k++) {
            int ky = k / 3, kx = k - ky * 3;
            bool rok = (rc == 1) || (rc == 0 ? (ky >= 1) : (ky <= 1));
            bool cok = (ccl == 1) || (ccl == 0 ? (kx >= 1) : (kx <= 1));
            if (rok && cok) {
                #pragma unroll
                for (int z = 0; z < 8; z++) out[z] += W8[z * 1152 + o * 9 + k];
            }
        }
        float4* dst = (float4*)&g_T[cls * 16384 + o * 128 + chunk * 8];
        dst[0] = make_float4(out[0], out[1], out[2], out[3]);
        dst[1] = make_float4(out[4], out[5], out[6], out[7]);
    }
}

// ======================= K0b: per-fj-row column sums =======================
__global__ __launch_bounds__(128) void a0_kernel() {
    int nb = 200 + blockIdx.x;
    int o = threadIdx.x;
    int s = nb * 256;
    int rem = s % 400;
    int g0 = 400 - rem; if (g0 > 256) g0 = 256;
    float a0 = 0.f, a1 = 0.f;
    for (int cp = 0; cp < 256; cp++) {
        float w = g_wr1ft[cp * CC + o];
        if (cp < g0) a0 += w; else a1 += w;
    }
    g_A0[blockIdx.x * CC + o] = a0;
    g_A1[blockIdx.x * CC + o] = a1;
}

// ======================= K1: feat (4 pixels/CTA) =======================
__global__ __launch_bounds__(128) void feat_kernel(const float* __restrict__ x) {
    __shared__ float4 xs4[CC];
    int bg = blockIdx.x;
    int b = bg / 100; int g = bg - b * 100;
    int c = threadIdx.x;
    xs4[c] = *(const float4*)&x[(b * CC + c) * CHW + g * 4];
    __syncthreads();
    float a0 = g_bias1[c], a1 = a0, a2 = a0, a3 = a0;
    #pragma unroll 4
    for (int k = 0; k < CC; k++) {
        float w = g_w1t[k * CC + c];
        float4 xv = xs4[k];
        a0 = fmaf(w, xv.x, a0);
        a1 = fmaf(w, xv.y, a1);
        a2 = fmaf(w, xv.z, a2);
        a3 = fmaf(w, xv.w, a3);
    }
    float f0 = siluf(a0), f1 = siluf(a1), f2 = siluf(a2), f3 = siluf(a3);
    int j0 = g * 4;
    g_feat[(b * CHW + j0 + 0) * CC + c] = f0;
    g_feat[(b * CHW + j0 + 1) * CC + c] = f1;
    g_feat[(b * CHW + j0 + 2) * CC + c] = f2;
    g_feat[(b * CHW + j0 + 3) * CC + c] = f3;
    *(float4*)&g_featT[(b * CC + c) * CHW + j0] = make_float4(f0, f1, f2, f3);
}

// ======================= K2: fi rows (2 rows/CTA, cp.async staging) ========
#define FI_GS    0                  // 512 floats = 2048
#define FI_PART  2048               // 256 floats = 1024
#define FI_R1T   3072               // 256 floats = 1024
#define FI_SVAL  4096               // 18 floats (pad 128)
#define FI_REDQ  4224               // [2h][9cls][2r][128] = 4608 floats = 18432
#define FI_REDS  22656              // 2304 floats = 9216
#define FI_STAGE 31872              // 2 x 36864 = 73728
#define FI_SMEM  105600

__global__ __launch_bounds__(256) void relation_fi_kernel() {
    extern __shared__ char fsm[];
    uint32_t sbase = smem_to_u32(fsm);
    float* gs     = (float*)(fsm + FI_GS);
    float* partA  = (float*)(fsm + FI_PART);
    float* r1T    = (float*)(fsm + FI_R1T);
    float* sval   = (float*)(fsm + FI_SVAL);
    float* redq   = (float*)(fsm + FI_REDQ);
    float* redsum = (float*)(fsm + FI_REDS);

    int bg = blockIdx.x;               // 0..199
    int b = bg / 100; int g = bg - b * 100;   // rows nb = 2g, 2g+1
    int t = threadIdx.x;

    // ---- prestage chunks 0,1 of g_T (overlaps with phase A) ----
    // chunk c: T[cls][oo=8c..8c+8][all o2], smem layout [(cls*8+u)*128 + o2]
    {
        #pragma unroll
        for (int j = 0; j < 9; j++) {
            int idx = t + j * 256;
            int cls = idx >> 8; int rem = idx & 255;
            int u = rem >> 5; int o2g = rem & 31;
            cp_async16(sbase + FI_STAGE + idx * 16,
                       g_T + cls * 16384 + u * 128 + o2g * 4);
        }
        CP_COMMIT();
        #pragma unroll
        for (int j = 0; j < 9; j++) {
            int idx = t + j * 256;
            int cls = idx >> 8; int rem = idx & 255;
            int u = rem >> 5; int o2g = rem & 31;
            cp_async16(sbase + FI_STAGE + 36864 + idx * 16,
                       g_T + cls * 16384 + (8 + u) * 128 + o2g * 4);
        }
        CP_COMMIT();
    }

    // ---- load both rows' 256-slices ----
    const float* src = g_featT + b * (CC * CHW) + g * 512;
    gs[t] = src[t];
    gs[t + 256] = src[t + 256];
    __syncthreads();

    // ---- phase A: r1[r][o] = silu(sum_cp wr1ft[cp][o]*gs[r][cp] + b[o]) ----
    {
        int o = t & 127, hb = t >> 7;
        float acc0 = hb ? 0.f : g_biasr1[o];
        float acc1 = acc0;
        int cp0 = hb * 128;
        #pragma unroll 4
        for (int cp = cp0; cp < cp0 + 128; cp++) {
            float w = g_wr1ft[cp * CC + o];
            acc0 = fmaf(w, gs[cp], acc0);
            acc1 = fmaf(w, gs[256 + cp], acc1);
        }
        if (hb) { partA[o] = acc0; partA[128 + o] = acc1; }
        __syncthreads();
        if (!hb) {
            r1T[o * 2 + 0] = siluf(acc0 + partA[o]);
            r1T[o * 2 + 1] = siluf(acc1 + partA[128 + o]);
        }
    }
    __syncthreads();

    // ---- phase B: thread = (o2 = t&127, h = t>>7), oo in [64h, 64h+64) ----
    int o2 = t & 127, h = t >> 7;
    float acc[9][2];
    #pragma unroll
    for (int cls = 0; cls < 9; cls++) { acc[cls][0] = 0.f; acc[cls][1] = 0.f; }

    for (int c = 0; c < 16; c++) {
        if (c == 15) { CP_WAIT0(); } else { CP_WAIT1(); }
        __syncthreads();
        const float* buf = (const float*)(fsm + FI_STAGE + (c & 1) * 36864);
        if ((c >> 3) == h) {
            #pragma unroll
            for (int u = 0; u < 8; u++) {
                int oo = c * 8 + u;
                float2 rv = *(float2*)&r1T[oo * 2];
                #pragma unroll
                for (int cls = 0; cls < 9; cls++) {
                    float tv = buf[(cls * 8 + u) * 128 + o2];
                    acc[cls][0] = fmaf(tv, rv.x, acc[cls][0]);
                    acc[cls][1] = fmaf(tv, rv.y, acc[cls][1]);
                }
            }
        }
        __syncthreads();
        if (c + 2 < 16) {
            int oo0 = (c + 2) * 8;
            uint32_t dbase = sbase + FI_STAGE + (c & 1) * 36864;
            #pragma unroll
            for (int j = 0; j < 9; j++) {
                int idx = t + j * 256;
                int cls = idx >> 8; int rem = idx & 255;
                int u = rem >> 5; int o2g = rem & 31;
                cp_async16(dbase + idx * 16,
                           g_T + cls * 16384 + (oo0 + u) * 128 + o2g * 4);
            }
            CP_COMMIT();
        }
    }

    // write partials
    #pragma unroll
    for (int cls = 0; cls < 9; cls++) {
        redq[h * 2304 + (cls * 2 + 0) * 128 + o2] = acc[cls][0];
        redq[h * 2304 + (cls * 2 + 1) * 128 + o2] = acc[cls][1];
    }
    __syncthreads();

    // combine halves + bias + silu + *w3
    for (int item = t; item < 2304; item += 256) {
        float v = redq[item] + redq[2304 + item];
        int o = item & 127;
        redsum[item] = g_wr3[o] * siluf(v + g_biasr2[o]);
    }
    __syncthreads();
    if (t < 18) {
        float s = g_bias3s[0];
        for (int o = 0; o < 128; o++) s += redsum[t * 128 + o];
        sval[t] = siluf(s);
    }
    __syncthreads();

    for (int idx = t; idx < 800; idx += 256) {
        int r = idx / 400; int j = idx - r * 400;
        int y = j / 20, xp = j - y * 20;
        int rc = (y == 0) ? 0 : (y == 19 ? 2 : 1);
        int ccl = (xp == 0) ? 0 : (xp == 19 ? 2 : 1);
        g_scores[(b * CHW + g * 2 + r) * CHW + j] = sval[(rc * 3 + ccl) * 2 + r];
    }
}

// ======================= K3: fj rows via mma.sync bf16 =======================
#define PITCH 272
#define OFF_A0    0
#define OFF_A1    512
#define OFF_BS    1024
#define OFF_BR2   1536
#define OFF_W3    2048
#define OFF_B3    2560
#define OFF_PART  2576
#define OFF_F0    (OFF_PART + 2048)
#define OFF_F1    (OFF_F0 + 1600)
#define OFF_LUT   (OFF_F1 + 1600)
#define OFF_WST0  (OFF_LUT + 16384)
#define OFF_WST1  (OFF_WST0 + 17408)
#define OFF_R1P   (OFF_WST1 + 17408)
#define FJ_SMEM   (OFF_R1P + 151776)

__global__ __launch_bounds__(256, 1) void relation_fj_mma_kernel() {
    extern __shared__ char smem[];
    uint32_t sbase = smem_to_u32(smem);
    float* a0s  = (float*)(smem + OFF_A0);
    float* a1s  = (float*)(smem + OFF_A1);
    float* bss  = (float*)(smem + OFF_BS);
    float* br2s = (float*)(smem + OFF_BR2);
    float* w3s  = (float*)(smem + OFF_W3);
    float* b3s  = (float*)(smem + OFF_B3);
    float* part = (float*)(smem + OFF_PART);
    float* f0s  = (float*)(smem + OFF_F0);
    float* f1s  = (float*)(smem + OFF_F1);
    const float2* lutp = (const float2*)(smem + OFF_LUT);
    char* r1pb = smem + OFF_R1P;

    int bi = blockIdx.x;
    int b = bi / 200; int nbr = bi - b * 200;
    int nb = 200 + nbr;
    int t = threadIdx.x;
    int w = t >> 5;
    int lane = t & 31;

    int s = nb * 256;
    int rem = s % 400;
    int g0 = 400 - rem; if (g0 > 256) g0 = 256;
    int cc0 = s / 400 - 128;
    int cc1 = (g0 < 256) ? (cc0 + 1) : cc0;

    if (t < CC) {
        a0s[t] = g_A0[nbr * CC + t];
        a1s[t] = g_A1[nbr * CC + t];
        bss[t] = g_biasr1[t];
        br2s[t] = g_biasr2[t];
        w3s[t] = g_wr3[t];
        if (t == 0) b3s[0] = g_bias3s[0];
    }
    {
        const float* f0p = g_featT + (b * CC + cc0) * CHW;
        const float* f1p = g_featT + (b * CC + cc1) * CHW;
        for (int j = t; j < CHW; j += 256) { f0s[j] = f0p[j]; f1s[j] = f1p[j]; }
    }
    for (int i = t; i < 2048; i += 256)
        ((float2*)(smem + OFF_LUT))[i] = g_lut[i];

    for (int i = t; i < (558 * PITCH) / 16; i += 256)
        ((uint4*)r1pb)[i] = make_uint4(0, 0, 0, 0);
    __syncthreads();

    for (int idx = t; idx < 400 * 64; idx += 256) {
        int j = idx >> 6, cp = idx & 63; int c = cp * 2;
        int y = j / 20, xx = j - y * 20;
        int u = 23 + (y + 1) * 22 + (xx + 1);
        float f0 = f0s[j], f1 = f1s[j];
        float t0 = fmaf(a0s[c], f0, fmaf(a1s[c], f1, bss[c]));
        float t1 = fmaf(a0s[c + 1], f0, fmaf(a1s[c + 1], f1, bss[c + 1]));
        __nv_bfloat162 h2 = __floats2bfloat162_rn(lut_silu(lutp, t0), lut_silu(lutp, t1));
        *(unsigned*)(r1pb + u * PITCH + cp * 4) = *(unsigned*)&h2;
    }

    int lrow = lane & 15;
    int lcol = lane >> 4;
    int brow = (lane & 7) + ((lane >> 4) << 3);
    int bcol = ((lane >> 3) & 1) * 16;
    uint32_t r1addr = sbase + OFF_R1P;

    float bias3 = 0.f;

    for (int npass = 0; npass < 2; npass++) {
        float acc[4][8][4];
        #pragma unroll
        for (int mf = 0; mf < 4; mf++)
            #pragma unroll
            for (int nf = 0; nf < 8; nf++)
                #pragma unroll
                for (int q = 0; q < 4; q++) acc[mf][nf][q] = 0.f;

        uint4 wreg[4];
        {
            const uint4* wsrc = (const uint4*)(g_wcv + (0 * CC + npass * 64) * CC);
            #pragma unroll
            for (int q = 0; q < 4; q++) wreg[q] = wsrc[t + q * 256];
        }

        for (int tap = 0; tap < 9; tap++) {
            char* wb = smem + ((tap & 1) ? OFF_WST1 : OFF_WST0);
            #pragma unroll
            for (int q = 0; q < 4; q++) {
                int idx = t + q * 256;
                int r = idx >> 4, ch16 = idx & 15;
                *(uint4*)(wb + r * PITCH + ch16 * 16) = wreg[q];
            }
            if (tap < 8) {
                const uint4* wsrc = (const uint4*)(g_wcv + ((tap + 1) * CC + npass * 64) * CC);
                #pragma unroll
                for (int q = 0; q < 4; q++) wreg[q] = wsrc[t + q * 256];
            }
            __syncthreads();

            int dy = tap / 3 - 1, dx = tap - (tap / 3) * 3 - 1;
            int delta = dy * 22 + dx;
            uint32_t abase = r1addr + (uint32_t)((23 + delta + w * 64 + lrow) * PITCH + lcol * 16);
            uint32_t bbase = sbase + ((tap & 1) ? OFF_WST1 : OFF_WST0)
                           + (uint32_t)(brow * PITCH + bcol);

            #pragma unroll 2
            for (int k16 = 0; k16 < 8; k16++) {
                unsigned af[4][4], bf[4][4];
                #pragma unroll
                for (int mf = 0; mf < 4; mf++)
                    ldsm_x4(af[mf], abase + mf * 16 * PITCH + k16 * 32);
                #pragma unroll
                for (int ng = 0; ng < 4; ng++)
                    ldsm_x4(bf[ng], bbase + ng * 16 * PITCH + k16 * 32);
                #pragma unroll
                for (int mf = 0; mf < 4; mf++)
                    #pragma unroll
                    for (int nf = 0; nf < 8; nf++)
                        mma16816(acc[mf][nf], af[mf], &bf[nf >> 1][(nf & 1) * 2]);
            }
        }

        if (npass == 1) bias3 = b3s[0];
        float rs[4][2];
        #pragma unroll
        for (int mf = 0; mf < 4; mf++) { rs[mf][0] = 0.f; rs[mf][1] = 0.f; }
        #pragma unroll
        for (int nf = 0; nf < 8; nf++) {
            int c2 = npass * 64 + nf * 8 + (lane & 3) * 2;
            float wa = w3s[c2], wb2 = w3s[c2 + 1];
            float ba = br2s[c2], bb = br2s[c2 + 1];
            #pragma unroll
            for (int mf = 0; mf < 4; mf++) {
                rs[mf][0] += wa * lut_silu(lutp, acc[mf][nf][0] + ba)
                           + wb2 * lut_silu(lutp, acc[mf][nf][1] + bb);
                rs[mf][1] += wa * lut_silu(lutp, acc[mf][nf][2] + ba)
                           + wb2 * lut_silu(lutp, acc[mf][nf][3] + bb);
            }
        }
        #pragma unroll
        for (int mf = 0; mf < 4; mf++) {
            #pragma unroll
            for (int hh = 0; hh < 2; hh++) {
                float v = rs[mf][hh];
                v += __shfl_xor_sync(0xFFFFFFFF, v, 1);
                v += __shfl_xor_sync(0xFFFFFFFF, v, 2);
                if ((lane & 3) == 0) {
                    int m0 = w * 64 + mf * 16 + (lane >> 2) + hh * 8;
                    if (npass == 0) {
                        part[m0] = v;
                    } else {
                        if (m0 < 484) {
                            int y = m0 / 22, xx = m0 - y * 22;
                            if (y >= 1 && y < 21 && xx >= 1 && xx < 21) {
                                int p = (y - 1) * 20 + (xx - 1);
                                float sc = bias3 + part[m0] + v;
                                g_scores[(b * CHW + nb) * CHW + p] = lut_silu(lutp, sc);
                            }
                        }
                    }
                }
            }
        }
        __syncthreads();
    }
}

// ======================= K4: att (4 rows/CTA) + CBS2 + residual ============
__global__ __launch_bounds__(128) void att_kernel(const float* __restrict__ x,
                                                  float* __restrict__ out) {
    __shared__ float sc[4][CHW];
    __shared__ float at[4][CC];
    int bg = blockIdx.x;
    int b = bg / 100; int g = bg - b * 100;
    int t = threadIdx.x;
    const float* srow = g_scores + (b * CHW + g * 4) * CHW;
    for (int idx = t; idx < 4 * CHW; idx += 128) {
        int r = idx / CHW;
        sc[r][idx - r * CHW] = srow[idx];
    }
    __syncthreads();
    float a0 = 0.f, a1 = 0.f, a2 = 0.f, a3 = 0.f;
    const float* fb = g_feat + b * CHW * CC;
    #pragma unroll 4
    for (int j = 0; j < CHW; j++) {
        float fv = fb[j * CC + t];
        a0 = fmaf(sc[0][j], fv, a0);
        a1 = fmaf(sc[1][j], fv, a1);
        a2 = fmaf(sc[2][j], fv, a2);
        a3 = fmaf(sc[3][j], fv, a3);
    }
    at[0][t] = a0; at[1][t] = a1; at[2][t] = a2; at[3][t] = a3;
    __syncthreads();
    float o0 = g_bias2[t], o1 = o0, o2 = o0, o3 = o0;
    #pragma unroll 4
    for (int k = 0; k < CC; k++) {
        float w = g_w2t[k * CC + t];
        o0 = fmaf(w, at[0][k], o0);
        o1 = fmaf(w, at[1][k], o1);
        o2 = fmaf(w, at[2][k], o2);
        o3 = fmaf(w, at[3][k], o3);
    }
    int obase = (b * CC + t) * CHW + g * 4;
    float4 xv = *(const float4*)&x[obase];
    float4 ov = make_float4(siluf(o0) + xv.x, siluf(o1) + xv.y,
                            siluf(o2) + xv.z, siluf(o3) + xv.w);
    *(float4*)&out[obase] = ov;
}

// ======================= launch =======================
extern "C" void kernel_launch(void* const* d_in, const int* in_sizes, int n_in,
                              void* d_out, int out_size) {
    (void)in_sizes; (void)n_in; (void)out_size;
    Params P;
    for (int i = 0; i < 26; i++) P.p[i] = (const float*)d_in[i];
    const float* x = (const float*)d_in[0];
    float* out = (float*)d_out;

    fold_kernel<<<64, 256>>>(P);
    buildT_kernel<<<16, 256>>>((const float*)d_in[16], (const float*)d_in[17],
                               (const float*)d_in[20]);
    a0_kernel<<<200, 128>>>();
    feat_kernel<<<CB * 100, 128>>>(x);

    cudaFuncSetAttribute(relation_fi_kernel,
                         cudaFuncAttributeMaxDynamicSharedMemorySize, FI_SMEM);
    relation_fi_kernel<<<CB * 100, 256, FI_SMEM>>>();

    cudaFuncSetAttribute(relation_fj_mma_kernel,
                         cudaFuncAttributeMaxDynamicSharedMemorySize, FJ_SMEM);
    relation_fj_mma_kernel<<<CB * 200, 256, FJ_SMEM>>>();

    att_kernel<<<CB * 100, 128>>>(x, out);
}